// round 2
// baseline (speedup 1.0000x reference)
#include <cuda_runtime.h>
#include <cuda_bf16.h>

// IDWT3D: 3D inverse Haar wavelet synthesis, N=256, channels=2.
// Input  x: [1, 128, 128, 128, 16]  (8 octant subbands x 2 channels, channel-stacked)
//         subband order in channel dim: LLL,LLH,LHL,LHH,HLL,HLH,HHL,HHH
//         (letters map to axes (1,2,3); L = low half, H = high half)
// Output:  [1, 256, 256, 256, 2]
//
// S = A^T for Haar (dec_lo=[r,r], dec_hi=[-r,r], r=1/sqrt(2)) implies per axis:
//   out[2i]   = r*(a[i] - d[i])
//   out[2i+1] = r*(a[i] + d[i])
// Separable over 3 axes -> per-voxel 3-level butterfly scaled by r^3.
// Purely HBM-bound: 128 MiB in + 128 MiB out, each byte touched once.

#define NH 128            // half size per axis
#define R3 0.35355339059327378f   // (1/sqrt(2))^3

__global__ void __launch_bounds__(256)
idwt3d_haar_kernel(const float* __restrict__ x, float* __restrict__ out)
{
    const int t = blockIdx.x * 256 + threadIdx.x;    // 0 .. 128^3-1
    const int k = t & (NH - 1);
    const int j = (t >> 7) & (NH - 1);
    const int i = t >> 14;

    // 16 contiguous floats per voxel: 4x float4, fully coalesced (2 KiB/warp).
    const float4* __restrict__ xin = reinterpret_cast<const float4*>(x) + (size_t)t * 4;
    const float4 p0 = xin[0];   // LLL(c0,c1), LLH(c0,c1)
    const float4 p1 = xin[1];   // LHL, LHH
    const float4 p2 = xin[2];   // HLL, HLH
    const float4 p3 = xin[3];   // HHL, HHH

    // v[oct][ch], oct = 4*e1 + 2*e2 + e3  (e=0:L, e=1:H)
    float v[8][2] = {
        {p0.x, p0.y}, {p0.z, p0.w},
        {p1.x, p1.y}, {p1.z, p1.w},
        {p2.x, p2.y}, {p2.z, p2.w},
        {p3.x, p3.y}, {p3.z, p3.w}
    };

    // Stage 1: axis-3 butterfly (e3 -> s3): s3=0: L-H, s3=1: L+H
    float t3[2][2][2][2];   // [e1][e2][s3][ch]
    #pragma unroll
    for (int e1 = 0; e1 < 2; ++e1)
        #pragma unroll
        for (int e2 = 0; e2 < 2; ++e2)
            #pragma unroll
            for (int ch = 0; ch < 2; ++ch) {
                const float lo = v[4*e1 + 2*e2 + 0][ch];
                const float hi = v[4*e1 + 2*e2 + 1][ch];
                t3[e1][e2][0][ch] = lo - hi;
                t3[e1][e2][1][ch] = lo + hi;
            }

    // Stage 2: axis-2 butterfly (e2 -> s2)
    float t2[2][2][2][2];   // [e1][s2][s3][ch]
    #pragma unroll
    for (int e1 = 0; e1 < 2; ++e1)
        #pragma unroll
        for (int s3 = 0; s3 < 2; ++s3)
            #pragma unroll
            for (int ch = 0; ch < 2; ++ch) {
                const float lo = t3[e1][0][s3][ch];
                const float hi = t3[e1][1][s3][ch];
                t2[e1][0][s3][ch] = lo - hi;
                t2[e1][1][s3][ch] = lo + hi;
            }

    // Stage 3: axis-1 butterfly (e1 -> s1), fused r^3 scale
    float t1[2][2][2][2];   // [s1][s2][s3][ch]
    #pragma unroll
    for (int s2 = 0; s2 < 2; ++s2)
        #pragma unroll
        for (int s3 = 0; s3 < 2; ++s3)
            #pragma unroll
            for (int ch = 0; ch < 2; ++ch) {
                const float lo = t2[0][s2][s3][ch];
                const float hi = t2[1][s2][s3][ch];
                t1[0][s2][s3][ch] = R3 * (lo - hi);
                t1[1][s2][s3][ch] = R3 * (lo + hi);
            }

    // Stores: out[y, x, z, c] with y=2i+s1, x=2j+s2, z in {2k,2k+1}, c in {0,1}.
    // (z,c) quad for fixed (s1,s2) = 4 contiguous floats -> one float4.
    // float4 index = ((2i+s1)*256 + (2j+s2))*128 + k  (512 B contiguous per warp/store)
    float4* __restrict__ out4 = reinterpret_cast<float4*>(out);
    const int yb = 2 * i;
    const int xb = 2 * j;
    #pragma unroll
    for (int s1 = 0; s1 < 2; ++s1)
        #pragma unroll
        for (int s2 = 0; s2 < 2; ++s2) {
            float4 w;
            w.x = t1[s1][s2][0][0];
            w.y = t1[s1][s2][0][1];
            w.z = t1[s1][s2][1][0];
            w.w = t1[s1][s2][1][1];
            const size_t idx = ((size_t)(yb + s1) * 256 + (xb + s2)) * 128 + k;
            out4[idx] = w;
        }
}

extern "C" void kernel_launch(void* const* d_in, const int* in_sizes, int n_in,
                              void* d_out, int out_size)
{
    const float* x = (const float*)d_in[0];   // [1,128,128,128,16] fp32
    float* out = (float*)d_out;               // [1,256,256,256,2] fp32
    (void)in_sizes; (void)n_in; (void)out_size;

    const int total = NH * NH * NH;           // 2,097,152 voxels
    idwt3d_haar_kernel<<<total / 256, 256>>>(x, out);
}